// round 1
// baseline (speedup 1.0000x reference)
#include <cuda_runtime.h>
#include <math.h>

#define BIGF 1e10f
#define WANISO 0.096f

// Scratch: 6 distance fields (2 batches x 3 labels) of 64^3 floats = 6 MB.
__device__ float g_F[6 * 262144];
__device__ double g_part[512];

// ---------------------------------------------------------------------------
// Kernel 1: initialize fields F[b][L][v] = (y[b][v]==L) ? 0 : BIG
// ---------------------------------------------------------------------------
__global__ void init_fields(const int* __restrict__ y) {
    int idx = blockIdx.x * blockDim.x + threadIdx.x;   // 0 .. 6*262144-1
    int v = idx & 262143;
    int field = idx >> 18;       // b*3 + L
    int b = field / 3;
    int L = field - b * 3;
    int lab = y[(b << 18) + v];
    g_F[idx] = (lab == L) ? 0.0f : BIGF;
}

// ---------------------------------------------------------------------------
// Min-plus pass along one axis, in place on g_F.
//   JS = stride of the transform (j / output) axis
//   LS = stride of the 32-wide lane axis
//   OS = stride of the remaining (outer) axis
// Block = 128 threads; block handles a 64(j) x 32(lane) slice.
// Each thread computes 16 outputs i = ybase..ybase+15 of one lane's line:
//   g[i] = min_j  f[j] + (W*(i-j))^2
// Inner loop steps j by 4: one LDS.128 for f, 5 warp-uniform LDS.128 for the
// 20-entry signed distance-squared window (provably 16B-aligned).
// ---------------------------------------------------------------------------
template<int JS, int LS, int OS, bool JCONTIG>
__global__ void __launch_bounds__(128) minplus_pass() {
    __shared__ __align__(16) float s[32][68];   // [lane][j], pad 4 for LDS.128
    __shared__ __align__(16) float tabs[128];   // tabs[i] = (W*(i-63))^2

    int tid = threadIdx.x;
    {
        float d = (float)(tid - 63);
        tabs[tid] = (WANISO * d) * (WANISO * d);
    }

    int bi = blockIdx.x;          // 0..767
    int field = bi >> 7;          // /128 -> 6 fields
    int rem = bi & 127;
    int outer = rem >> 1;         // 0..63
    int half = rem & 1;           // which 32-lane half
    float* F = g_F + field * 262144 + outer * OS + half * 32 * LS;

    // cooperative load of the slice into shared (coalesced on the unit-stride axis)
    for (int idx = tid; idx < 2048; idx += 128) {
        int j, lane;
        if (JCONTIG) { j = idx & 63; lane = idx >> 6; }
        else         { lane = idx & 31; j = idx >> 5; }
        s[lane][j] = F[lane * LS + j * JS];
    }
    __syncthreads();

    int lane = tid & 31;
    int ybase = (tid >> 5) << 4;  // 0,16,32,48 (warp-uniform)

    float g[16];
#pragma unroll
    for (int k = 0; k < 16; k++) g[k] = BIGF;

    const float* srow = &s[lane][0];

#pragma unroll 1
    for (int jb = 0; jb < 64; jb += 4) {
        float4 f = *reinterpret_cast<const float4*>(srow + jb);
        // window start: ybase - jb + 60  (multiple of 4, in [0,108])
        const float* wb = &tabs[ybase - jb + 60];
        float w[20];
#pragma unroll
        for (int m = 0; m < 5; m++) {
            float4 t = reinterpret_cast<const float4*>(wb)[m];
            w[4 * m + 0] = t.x; w[4 * m + 1] = t.y;
            w[4 * m + 2] = t.z; w[4 * m + 3] = t.w;
        }
        // pair (k, t): d = (ybase+k) - (jb+t); tab index offset = k - t + 3
#pragma unroll
        for (int k = 0; k < 16; k++) {
            float a0 = f.x + w[k + 3];
            float a1 = f.y + w[k + 2];
            float a2 = f.z + w[k + 1];
            float a3 = f.w + w[k + 0];
            g[k] = fminf(g[k], fminf(fminf(a0, a1), fminf(a2, a3)));
        }
    }

#pragma unroll
    for (int k = 0; k < 16; k++) {
        F[lane * LS + (ybase + k) * JS] = g[k];
    }
}

// ---------------------------------------------------------------------------
// Kernel: fused gather + loss partial reduction (deterministic two-stage)
// ---------------------------------------------------------------------------
__global__ void __launch_bounds__(256) reduce_kernel(const float* __restrict__ x,
                                                     const int* __restrict__ y) {
    int tid = threadIdx.x;
    int gid = blockIdx.x * 256 + tid;
    double acc = 0.0;
#pragma unroll
    for (int r = 0; r < 4; r++) {
        int idx = gid + r * 131072;          // 512*256 = 131072 threads total
        int b = idx >> 18;
        int v = idx & 262143;
        int lab = y[idx];
        float f0 = g_F[(b * 3 + 0) * 262144 + v];
        float f1 = g_F[(b * 3 + 1) * 262144 + v];
        float f2 = g_F[(b * 3 + 2) * 262144 + v];
        float m0 = (lab == 0) ? BIGF : f0;
        float m1 = (lab == 1) ? BIGF : f1;
        float m2 = (lab == 2) ? BIGF : f2;
        float d2 = fminf(m0, fminf(m1, m2));
        float dt = sqrtf(d2) + 1.0f;
        float x1 = x[(b * 3 + 1) * 262144 + v];
        float x2 = x[(b * 3 + 2) * 262144 + v];
        float t1 = (lab == 1) ? (1.0f - x1) * dt : x1 * dt;
        float t2 = (lab == 2) ? (1.0f - x2) * dt : x2 * dt;
        acc += (double)(t1 + t2);
    }
    // warp reduce
#pragma unroll
    for (int o = 16; o > 0; o >>= 1)
        acc += __shfl_down_sync(0xffffffffu, acc, o);
    __shared__ double ssum[8];
    if ((tid & 31) == 0) ssum[tid >> 5] = acc;
    __syncthreads();
    if (tid < 8) {
        double a = ssum[tid];
#pragma unroll
        for (int o = 4; o > 0; o >>= 1)
            a += __shfl_down_sync(0xffu, a, o);
        if (tid == 0) g_part[blockIdx.x] = a;
    }
}

__global__ void final_kernel(float* __restrict__ out) {
    int tid = threadIdx.x;   // 512 threads
    double a = g_part[tid];
#pragma unroll
    for (int o = 16; o > 0; o >>= 1)
        a += __shfl_down_sync(0xffffffffu, a, o);
    __shared__ double ss[16];
    if ((tid & 31) == 0) ss[tid >> 5] = a;
    __syncthreads();
    if (tid < 16) {
        double v = ss[tid];
#pragma unroll
        for (int o = 8; o > 0; o >>= 1)
            v += __shfl_down_sync(0xffffu, v, o);
        if (tid == 0) out[0] = (float)(v / 1048576.0 + 1e-5);
    }
}

// ---------------------------------------------------------------------------
// kernel_launch: init -> minplus z -> minplus y -> minplus x -> reduce -> final
// Volume linear index: z*4096 + y*64 + x  (per field)
// ---------------------------------------------------------------------------
extern "C" void kernel_launch(void* const* d_in, const int* in_sizes, int n_in,
                              void* d_out, int out_size) {
    const float* x = (const float*)d_in[0];   // (2,3,64,64,64) f32
    const int*   y = (const int*)d_in[1];     // (2,1,64,64,64) i32

    init_fields<<<6144, 256>>>(y);
    // axis 1 (z): JS=4096, lanes along x (LS=1), outer = y (OS=64)
    minplus_pass<4096, 1, 64, false><<<768, 128>>>();
    // axis 2 (y): JS=64, lanes along x (LS=1), outer = z (OS=4096)
    minplus_pass<64, 1, 4096, false><<<768, 128>>>();
    // axis 3 (x): JS=1, lanes along y (LS=64), outer = z (OS=4096)
    minplus_pass<1, 64, 4096, true><<<768, 128>>>();

    reduce_kernel<<<512, 256>>>(x, y);
    final_kernel<<<1, 512>>>((float*)d_out);
}

// round 3
// speedup vs baseline: 1.0975x; 1.0975x over previous
#include <cuda_runtime.h>
#include <math.h>

#define BIGF 1e10f
#define W2f  (0.096f * 0.096f)          // W^2
#define CWf  (2.0f * 0.096f * 0.096f)   // 2 W^2

// Scratch: 6 distance fields (2 batches x 3 labels) of 64^3 floats = 6 MB.
__device__ float g_F[6 * 262144];
__device__ double g_part[512];

// ---------------------------------------------------------------------------
// Core: for one lane's line held in shared (already shifted: p[j] = f[j]+W^2 j^2),
// compute 8 outputs i = ybase..ybase+7:
//     g[i] = min_j ( p[j] - 2W^2 j * i ) + W^2 i^2
// Per (i,j) pair: exactly 1 FFMA + 1 FMNMX -> perfect fma/alu dual-issue mix.
// ---------------------------------------------------------------------------
__device__ __forceinline__ void minplus_core(const float* __restrict__ srow,
                                             int ybase, float* __restrict__ gout) {
    float fi[8];
#pragma unroll
    for (int k = 0; k < 8; k++) fi[k] = (float)(ybase + k);
    float g[8];
#pragma unroll
    for (int k = 0; k < 8; k++) g[k] = BIGF;

#pragma unroll 2
    for (int jb = 0; jb < 64; jb += 8) {
        float4 pa = *reinterpret_cast<const float4*>(srow + jb);
        float4 pb = *reinterpret_cast<const float4*>(srow + jb + 4);
        float c0 = -CWf * (float)jb;
        float c1 = c0 - 1.0f * CWf;
        float c2 = c0 - 2.0f * CWf;
        float c3 = c0 - 3.0f * CWf;
        float c4 = c0 - 4.0f * CWf;
        float c5 = c0 - 5.0f * CWf;
        float c6 = c0 - 6.0f * CWf;
        float c7 = c0 - 7.0f * CWf;
#pragma unroll
        for (int k = 0; k < 8; k++) {
            float t0 = fmaf(c0, fi[k], pa.x);
            float t1 = fmaf(c1, fi[k], pa.y);
            float t2 = fmaf(c2, fi[k], pa.z);
            float t3 = fmaf(c3, fi[k], pa.w);
            float t4 = fmaf(c4, fi[k], pb.x);
            float t5 = fmaf(c5, fi[k], pb.y);
            float t6 = fmaf(c6, fi[k], pb.z);
            float t7 = fmaf(c7, fi[k], pb.w);
            float m01 = fminf(t0, t1);
            float m23 = fminf(t2, t3);
            float m45 = fminf(t4, t5);
            float m67 = fminf(t6, t7);
            float m   = fminf(fminf(m01, m23), fminf(m45, m67));
            g[k] = fminf(g[k], m);
        }
    }
#pragma unroll
    for (int k = 0; k < 8; k++)
        gout[k] = fmaf(W2f * fi[k], fi[k], g[k]);   // shift back: + W^2 i^2
}

// ---------------------------------------------------------------------------
// Pass 1 (z axis), fused with field init: reads labels y directly.
//   j = z (stride 4096), lane = x (stride 1), outer = y (stride 64)
// ---------------------------------------------------------------------------
__global__ void __launch_bounds__(256) minplus_z_first(const int* __restrict__ y) {
    __shared__ __align__(16) float s[32][68];   // [lane][j], pad 4: conflict-free LDS.128
    int tid = threadIdx.x;
    int bi = blockIdx.x;             // 0..767
    int field = bi >> 7;             // b*3 + L
    int rem = bi & 127;
    int outer = rem >> 1;            // y index
    int half = rem & 1;
    int b = field / 3;
    int L = field - 3 * b;

    const int* yb = y + (b << 18) + outer * 64 + half * 32;
    for (int idx = tid; idx < 2048; idx += 256) {
        int lane = idx & 31, j = idx >> 5;
        int lab = yb[j * 4096 + lane];
        float fj = (float)j;
        float base = (lab == L) ? 0.0f : BIGF;
        s[lane][j] = fmaf(W2f * fj, fj, base);   // p[j] = f[j] + W^2 j^2
    }
    __syncthreads();

    int lane = tid & 31;
    int ybase = (tid >> 5) << 3;     // 0,8,...,56
    float gout[8];
    minplus_core(&s[lane][0], ybase, gout);

    float* F = g_F + field * 262144 + outer * 64 + half * 32;
#pragma unroll
    for (int k = 0; k < 8; k++)
        F[lane + (ybase + k) * 4096] = gout[k];
}

// ---------------------------------------------------------------------------
// Generic in-place pass: JS = transform-axis stride, LS = lane stride,
// OS = outer stride. Block = 256 threads = one 64(j) x 32(lane) slice.
// ---------------------------------------------------------------------------
template<int JS, int LS, int OS, bool JCONTIG>
__global__ void __launch_bounds__(256) minplus_pass() {
    __shared__ __align__(16) float s[32][68];
    int tid = threadIdx.x;
    int bi = blockIdx.x;
    int field = bi >> 7;
    int rem = bi & 127;
    int outer = rem >> 1;
    int half = rem & 1;
    float* F = g_F + field * 262144 + outer * OS + half * 32 * LS;

    for (int idx = tid; idx < 2048; idx += 256) {
        int j, lane;
        if (JCONTIG) { j = idx & 63; lane = idx >> 6; }
        else         { lane = idx & 31; j = idx >> 5; }
        float fj = (float)j;
        s[lane][j] = fmaf(W2f * fj, fj, F[lane * LS + j * JS]);
    }
    __syncthreads();

    int lane = tid & 31;
    int ybase = (tid >> 5) << 3;
    float gout[8];
    minplus_core(&s[lane][0], ybase, gout);

#pragma unroll
    for (int k = 0; k < 8; k++)
        F[lane * LS + (ybase + k) * JS] = gout[k];
}

// ---------------------------------------------------------------------------
// Fused gather + loss partial reduction (deterministic two-stage)
// ---------------------------------------------------------------------------
__global__ void __launch_bounds__(256) reduce_kernel(const float* __restrict__ x,
                                                     const int* __restrict__ y) {
    int tid = threadIdx.x;
    int gid = blockIdx.x * 256 + tid;
    double acc = 0.0;
#pragma unroll
    for (int r = 0; r < 4; r++) {
        int idx = gid + r * 131072;          // 512*256 = 131072 threads total
        int b = idx >> 18;
        int v = idx & 262143;
        int lab = y[idx];
        float f0 = g_F[(b * 3 + 0) * 262144 + v];
        float f1 = g_F[(b * 3 + 1) * 262144 + v];
        float f2 = g_F[(b * 3 + 2) * 262144 + v];
        float m0 = (lab == 0) ? BIGF : f0;
        float m1 = (lab == 1) ? BIGF : f1;
        float m2 = (lab == 2) ? BIGF : f2;
        float d2 = fminf(m0, fminf(m1, m2));
        float dt = sqrtf(d2) + 1.0f;
        float x1 = x[(b * 3 + 1) * 262144 + v];
        float x2 = x[(b * 3 + 2) * 262144 + v];
        float t1 = (lab == 1) ? (1.0f - x1) * dt : x1 * dt;
        float t2 = (lab == 2) ? (1.0f - x2) * dt : x2 * dt;
        acc += (double)(t1 + t2);
    }
#pragma unroll
    for (int o = 16; o > 0; o >>= 1)
        acc += __shfl_down_sync(0xffffffffu, acc, o);
    __shared__ double ssum[8];
    if ((tid & 31) == 0) ssum[tid >> 5] = acc;
    __syncthreads();
    if (tid < 8) {
        double a = ssum[tid];
#pragma unroll
        for (int o = 4; o > 0; o >>= 1)
            a += __shfl_down_sync(0xffu, a, o);
        if (tid == 0) g_part[blockIdx.x] = a;
    }
}

__global__ void final_kernel(float* __restrict__ out) {
    int tid = threadIdx.x;   // 512 threads
    double a = g_part[tid];
#pragma unroll
    for (int o = 16; o > 0; o >>= 1)
        a += __shfl_down_sync(0xffffffffu, a, o);
    __shared__ double ss[16];
    if ((tid & 31) == 0) ss[tid >> 5] = a;
    __syncthreads();
    if (tid < 16) {
        double v = ss[tid];
#pragma unroll
        for (int o = 8; o > 0; o >>= 1)
            v += __shfl_down_sync(0xffffu, v, o);
        if (tid == 0) out[0] = (float)(v / 1048576.0 + 1e-5);
    }
}

// ---------------------------------------------------------------------------
// z -> y -> x passes (same order as reference), then fused loss reduce.
// Volume linear index: z*4096 + y*64 + x (per field).
// ---------------------------------------------------------------------------
extern "C" void kernel_launch(void* const* d_in, const int* in_sizes, int n_in,
                              void* d_out, int out_size) {
    const float* x = (const float*)d_in[0];   // (2,3,64,64,64) f32
    const int*   y = (const int*)d_in[1];     // (2,1,64,64,64) i32

    // axis z: j stride 4096, lanes along x (1), outer = y (64), fused init
    minplus_z_first<<<768, 256>>>(y);
    // axis y: j stride 64, lanes along x (1), outer = z (4096)
    minplus_pass<64, 1, 4096, false><<<768, 256>>>();
    // axis x: j stride 1, lanes along y (64), outer = z (4096)
    minplus_pass<1, 64, 4096, true><<<768, 256>>>();

    reduce_kernel<<<512, 256>>>(x, y);
    final_kernel<<<1, 512>>>((float*)d_out);
}